// round 1
// baseline (speedup 1.0000x reference)
#include <cuda_runtime.h>

#define BB 2
#define SS 4096
#define DD 512
#define HH 8
#define HDIM 64
#define MTOT (BB*SS)

// Scratch (allocation-free rule: device globals)
__device__ float g_q[BB*HH*SS*HDIM];
__device__ float g_k[BB*HH*SS*HDIM];
__device__ float g_v[BB*HH*SS*HDIM];
__device__ float g_attn[BB*SS*DD];

// ---------------------------------------------------------------------------
// NT GEMM: C[m,n] = sum_k A[m,k] * W[n,k] + bias[n]
// 64x64 tile, 256 threads, 4x4 micro-tile per thread, K-tile 16.
// blockIdx.z selects q/k/v weight; output written head-split [B,H,S,HD].
// ---------------------------------------------------------------------------
__global__ __launch_bounds__(256) void qkv_gemm(
    const float* __restrict__ X,
    const float* __restrict__ Wq, const float* __restrict__ bq,
    const float* __restrict__ Wk, const float* __restrict__ bk,
    const float* __restrict__ Wv, const float* __restrict__ bv)
{
    const float* W;
    const float* bias;
    float* out;
    int z = blockIdx.z;
    if (z == 0)      { W = Wq; bias = bq; out = g_q; }
    else if (z == 1) { W = Wk; bias = bk; out = g_k; }
    else             { W = Wv; bias = bv; out = g_v; }

    __shared__ float As[16][64];   // [k][m]
    __shared__ float Bs[16][64];   // [k][n]

    int tid = threadIdx.x;
    int tm = tid >> 4;             // 0..15
    int tn = tid & 15;             // 0..15
    int m0 = blockIdx.y * 64;
    int n0 = blockIdx.x * 64;
    int lr = tid >> 2;             // 0..63
    int lc = (tid & 3) << 2;       // 0,4,8,12

    const float* Aptr = X + (size_t)(m0 + lr) * DD + lc;
    const float* Wptr = W + (size_t)(n0 + lr) * DD + lc;

    float acc[4][4] = {};

    for (int k0 = 0; k0 < DD; k0 += 16) {
        float4 av = *(const float4*)(Aptr + k0);
        float4 wv = *(const float4*)(Wptr + k0);
        __syncthreads();
        As[lc + 0][lr] = av.x; As[lc + 1][lr] = av.y;
        As[lc + 2][lr] = av.z; As[lc + 3][lr] = av.w;
        Bs[lc + 0][lr] = wv.x; Bs[lc + 1][lr] = wv.y;
        Bs[lc + 2][lr] = wv.z; Bs[lc + 3][lr] = wv.w;
        __syncthreads();
        #pragma unroll
        for (int kk = 0; kk < 16; kk++) {
            float4 a4 = *(const float4*)&As[kk][tm * 4];
            float4 b4 = *(const float4*)&Bs[kk][tn * 4];
            float a[4] = {a4.x, a4.y, a4.z, a4.w};
            float b[4] = {b4.x, b4.y, b4.z, b4.w};
            #pragma unroll
            for (int i = 0; i < 4; i++)
                #pragma unroll
                for (int j = 0; j < 4; j++)
                    acc[i][j] = fmaf(a[i], b[j], acc[i][j]);
        }
    }

    int n = n0 + tn * 4;
    float4 bv4 = *(const float4*)&bias[n];
    int h = n >> 6;          // head
    int hd = n & 63;         // within-head dim (n0 multiple of 64 -> hd = 4*tn)
    #pragma unroll
    for (int i = 0; i < 4; i++) {
        int m = m0 + tm * 4 + i;
        int b = m >> 12;          // m / S
        int s = m & (SS - 1);
        float4 r;
        r.x = acc[i][0] + bv4.x;
        r.y = acc[i][1] + bv4.y;
        r.z = acc[i][2] + bv4.z;
        r.w = acc[i][3] + bv4.w;
        *(float4*)&out[(((size_t)(b * HH + h) * SS + s) << 6) + hd] = r;
    }
}

// ---------------------------------------------------------------------------
// Output projection GEMM: out = g_attn @ Wo^T + bo, flat [M, D] output
// ---------------------------------------------------------------------------
__global__ __launch_bounds__(256) void out_gemm(
    const float* __restrict__ Wo, const float* __restrict__ bo,
    float* __restrict__ out)
{
    __shared__ float As[16][64];
    __shared__ float Bs[16][64];

    int tid = threadIdx.x;
    int tm = tid >> 4;
    int tn = tid & 15;
    int m0 = blockIdx.y * 64;
    int n0 = blockIdx.x * 64;
    int lr = tid >> 2;
    int lc = (tid & 3) << 2;

    const float* Aptr = g_attn + (size_t)(m0 + lr) * DD + lc;
    const float* Wptr = Wo     + (size_t)(n0 + lr) * DD + lc;

    float acc[4][4] = {};

    for (int k0 = 0; k0 < DD; k0 += 16) {
        float4 av = *(const float4*)(Aptr + k0);
        float4 wv = *(const float4*)(Wptr + k0);
        __syncthreads();
        As[lc + 0][lr] = av.x; As[lc + 1][lr] = av.y;
        As[lc + 2][lr] = av.z; As[lc + 3][lr] = av.w;
        Bs[lc + 0][lr] = wv.x; Bs[lc + 1][lr] = wv.y;
        Bs[lc + 2][lr] = wv.z; Bs[lc + 3][lr] = wv.w;
        __syncthreads();
        #pragma unroll
        for (int kk = 0; kk < 16; kk++) {
            float4 a4 = *(const float4*)&As[kk][tm * 4];
            float4 b4 = *(const float4*)&Bs[kk][tn * 4];
            float a[4] = {a4.x, a4.y, a4.z, a4.w};
            float b[4] = {b4.x, b4.y, b4.z, b4.w};
            #pragma unroll
            for (int i = 0; i < 4; i++)
                #pragma unroll
                for (int j = 0; j < 4; j++)
                    acc[i][j] = fmaf(a[i], b[j], acc[i][j]);
        }
    }

    int n = n0 + tn * 4;
    float4 bv4 = *(const float4*)&bo[n];
    #pragma unroll
    for (int i = 0; i < 4; i++) {
        int m = m0 + tm * 4 + i;
        float4 r;
        r.x = acc[i][0] + bv4.x;
        r.y = acc[i][1] + bv4.y;
        r.z = acc[i][2] + bv4.z;
        r.w = acc[i][3] + bv4.w;
        *(float4*)&out[(size_t)m * DD + n] = r;
    }
}

// ---------------------------------------------------------------------------
// Flash attention per (b,h): 64 query rows per block, stream over 64-key tiles,
// online softmax. K stored XOR-swizzled for conflict-free reads; P overlays K.
// ---------------------------------------------------------------------------
__global__ __launch_bounds__(256) void flash_attn()
{
    __shared__ float Qs[64][64];   // natural [q][hd]; reads broadcast
    __shared__ float KP[64][64];   // K swizzled [kk][hd^ror2(kk)], later P [q][kk]
    __shared__ float Vs[64][64];   // natural [kk][hd]

    int tid = threadIdx.x;
    int bh = blockIdx.y;           // 0..15
    int q0 = blockIdx.x << 6;

    const float* Qb = g_q + (size_t)bh * SS * HDIM;
    const float* Kb = g_k + (size_t)bh * SS * HDIM;
    const float* Vb = g_v + (size_t)bh * SS * HDIM;

    int tm = tid >> 4;             // 0..15 (q micro-row group)
    int tn = tid & 15;             // 0..15 (key / hd micro-col group)

    int lrow = tid >> 4;           // 0..15 (loader row)
    int lcol = (tid & 15) << 2;    // 0..60 (loader col, float4)

    // load + scale Q tile
    const float scale = 0.125f;    // 1/sqrt(64)
    #pragma unroll
    for (int r = 0; r < 4; r++) {
        int row = lrow + 16 * r;
        float4 v = *(const float4*)&Qb[(size_t)(q0 + row) * HDIM + lcol];
        v.x *= scale; v.y *= scale; v.z *= scale; v.w *= scale;
        *(float4*)&Qs[row][lcol] = v;
    }

    float acc[4][4] = {};
    float mi[4], li[4];
    #pragma unroll
    for (int i = 0; i < 4; i++) { mi[i] = -1e30f; li[i] = 0.f; }

    // swizzle constants for the 4 key rows this thread reads
    int rj[4];
    #pragma unroll
    for (int j = 0; j < 4; j++) {
        int kn = tn * 4 + j;
        rj[j] = (kn >> 2) | ((kn & 3) << 4);   // ror2 of 6-bit index
    }

    const float* qp0 = &Qs[tm * 4 + 0][0];
    const float* qp1 = &Qs[tm * 4 + 1][0];
    const float* qp2 = &Qs[tm * 4 + 2][0];
    const float* qp3 = &Qs[tm * 4 + 3][0];
    const float* kp0 = &KP[tn * 4 + 0][0];
    const float* kp1 = &KP[tn * 4 + 1][0];
    const float* kp2 = &KP[tn * 4 + 2][0];
    const float* kp3 = &KP[tn * 4 + 3][0];
    const float* pp0 = &KP[tm * 4 + 0][0];
    const float* pp1 = &KP[tm * 4 + 1][0];
    const float* pp2 = &KP[tm * 4 + 2][0];
    const float* pp3 = &KP[tm * 4 + 3][0];

    for (int kt = 0; kt < SS / 64; kt++) {
        int kbase = kt << 6;

        float4 kv[4], vv[4];
        #pragma unroll
        for (int r = 0; r < 4; r++) {
            int row = lrow + 16 * r;
            kv[r] = *(const float4*)&Kb[(size_t)(kbase + row) * HDIM + lcol];
            vv[r] = *(const float4*)&Vb[(size_t)(kbase + row) * HDIM + lcol];
        }

        __syncthreads();   // previous PV done reading KP/Vs

        #pragma unroll
        for (int r = 0; r < 4; r++) {
            int row = lrow + 16 * r;
            int rr = (row >> 2) | ((row & 3) << 4);
            KP[row][(lcol + 0) ^ rr] = kv[r].x;
            KP[row][(lcol + 1) ^ rr] = kv[r].y;
            KP[row][(lcol + 2) ^ rr] = kv[r].z;
            KP[row][(lcol + 3) ^ rr] = kv[r].w;
            *(float4*)&Vs[row][lcol] = vv[r];
        }
        __syncthreads();

        // scores: sc[i][j] = Q[qrow i] . K[krow j]   (Q pre-scaled)
        float sc[4][4] = {};
        #pragma unroll 8
        for (int hd = 0; hd < 64; hd++) {
            float qv4[4] = { qp0[hd], qp1[hd], qp2[hd], qp3[hd] };
            float kv4[4] = { kp0[hd ^ rj[0]], kp1[hd ^ rj[1]],
                             kp2[hd ^ rj[2]], kp3[hd ^ rj[3]] };
            #pragma unroll
            for (int i = 0; i < 4; i++)
                #pragma unroll
                for (int j = 0; j < 4; j++)
                    sc[i][j] = fmaf(qv4[i], kv4[j], sc[i][j]);
        }

        // online softmax update (per q-row; rows owned by a 16-lane tn-group)
        #pragma unroll
        for (int i = 0; i < 4; i++) {
            float mx = fmaxf(fmaxf(sc[i][0], sc[i][1]), fmaxf(sc[i][2], sc[i][3]));
            #pragma unroll
            for (int off = 8; off > 0; off >>= 1)
                mx = fmaxf(mx, __shfl_xor_sync(0xffffffffu, mx, off));
            float mnew = fmaxf(mi[i], mx);
            float f = __expf(mi[i] - mnew);
            float rs = 0.f;
            #pragma unroll
            for (int j = 0; j < 4; j++) {
                sc[i][j] = __expf(sc[i][j] - mnew);   // reuse sc as P
                rs += sc[i][j];
            }
            #pragma unroll
            for (int off = 8; off > 0; off >>= 1)
                rs += __shfl_xor_sync(0xffffffffu, rs, off);
            li[i] = li[i] * f + rs;
            mi[i] = mnew;
            acc[i][0] *= f; acc[i][1] *= f; acc[i][2] *= f; acc[i][3] *= f;
        }

        __syncthreads();   // all done reading KP as K

        // write P natural [q][kk] into KP
        #pragma unroll
        for (int i = 0; i < 4; i++)
            #pragma unroll
            for (int j = 0; j < 4; j++)
                KP[tm * 4 + i][tn * 4 + j] = sc[i][j];
        __syncthreads();

        // PV: acc[i][j] += sum_kk P[qrow i][kk] * V[kk][hdcol j]
        #pragma unroll 8
        for (int kk = 0; kk < 64; kk++) {
            float p4[4] = { pp0[kk], pp1[kk], pp2[kk], pp3[kk] };
            float4 v4 = *(const float4*)&Vs[kk][tn * 4];
            float vj[4] = { v4.x, v4.y, v4.z, v4.w };
            #pragma unroll
            for (int i = 0; i < 4; i++)
                #pragma unroll
                for (int j = 0; j < 4; j++)
                    acc[i][j] = fmaf(p4[i], vj[j], acc[i][j]);
        }
    }

    // epilogue: O = acc / l, write to [B,S,D] layout for the output GEMM
    int b = bh >> 3;
    int h = bh & 7;
    #pragma unroll
    for (int i = 0; i < 4; i++) {
        float inv = 1.f / li[i];
        int q = q0 + tm * 4 + i;
        float4 r;
        r.x = acc[i][0] * inv;
        r.y = acc[i][1] * inv;
        r.z = acc[i][2] * inv;
        r.w = acc[i][3] * inv;
        *(float4*)&g_attn[(size_t)(b * SS + q) * DD + h * HDIM + tn * 4] = r;
    }
}

// ---------------------------------------------------------------------------
extern "C" void kernel_launch(void* const* d_in, const int* in_sizes, int n_in,
                              void* d_out, int out_size)
{
    (void)in_sizes; (void)n_in; (void)out_size;
    const float* x  = (const float*)d_in[0];
    const float* Wq = (const float*)d_in[1];
    const float* bq = (const float*)d_in[2];
    const float* Wk = (const float*)d_in[3];
    const float* bk = (const float*)d_in[4];
    const float* Wv = (const float*)d_in[5];
    const float* bv = (const float*)d_in[6];
    const float* Wo = (const float*)d_in[7];
    const float* bo = (const float*)d_in[8];
    float* out = (float*)d_out;

    dim3 gqkv(DD / 64, MTOT / 64, 3);     // (8, 128, 3)
    qkv_gemm<<<gqkv, 256>>>(x, Wq, bq, Wk, bk, Wv, bv);

    dim3 gat(SS / 64, BB * HH);           // (64, 16)
    flash_attn<<<gat, 256>>>();

    dim3 go(DD / 64, MTOT / 64);          // (8, 128)
    out_gemm<<<go, 256>>>(Wo, bo, out);
}

// round 2
// speedup vs baseline: 1.5757x; 1.5757x over previous
#include <cuda_runtime.h>

#define BB 2
#define SS 4096
#define DD 512
#define HH 8
#define HDIM 64
#define MTOT (BB*SS)

// Scratch (allocation-free rule: device globals)
__device__ float g_q[BB*HH*SS*HDIM];
__device__ float g_k[BB*HH*SS*HDIM];
__device__ float g_v[BB*HH*SS*HDIM];
__device__ float g_attn[BB*SS*DD];

// ---------------------------------------------------------------------------
// helpers: tf32 convert + m16n8k8 tf32 mma
// ---------------------------------------------------------------------------
__device__ __forceinline__ unsigned f2tf(float f) {
    unsigned u;
    asm("cvt.rna.tf32.f32 %0, %1;" : "=r"(u) : "f"(f));
    return u;
}

__device__ __forceinline__ void mma_tf32(float c[4],
    unsigned a0, unsigned a1, unsigned a2, unsigned a3,
    unsigned b0, unsigned b1)
{
    asm volatile(
        "mma.sync.aligned.m16n8k8.row.col.f32.tf32.tf32.f32 "
        "{%0,%1,%2,%3}, {%4,%5,%6,%7}, {%8,%9}, {%0,%1,%2,%3};"
        : "+f"(c[0]), "+f"(c[1]), "+f"(c[2]), "+f"(c[3])
        : "r"(a0), "r"(a1), "r"(a2), "r"(a3), "r"(b0), "r"(b1));
}

__device__ __forceinline__ void ld8(unsigned* dst, const float* base) {
    uint4 a = *(const uint4*)base;
    uint4 b = *(const uint4*)(base + 4);
    dst[0]=a.x; dst[1]=a.y; dst[2]=a.z; dst[3]=a.w;
    dst[4]=b.x; dst[5]=b.y; dst[6]=b.z; dst[7]=b.w;
}

// ---------------------------------------------------------------------------
// NT GEMM: C[m,n] = sum_k A[m,k] * W[n,k] + bias[n]  (fp32 SIMT, unchanged)
// ---------------------------------------------------------------------------
__global__ __launch_bounds__(256) void qkv_gemm(
    const float* __restrict__ X,
    const float* __restrict__ Wq, const float* __restrict__ bq,
    const float* __restrict__ Wk, const float* __restrict__ bk,
    const float* __restrict__ Wv, const float* __restrict__ bv)
{
    const float* W;
    const float* bias;
    float* out;
    int z = blockIdx.z;
    if (z == 0)      { W = Wq; bias = bq; out = g_q; }
    else if (z == 1) { W = Wk; bias = bk; out = g_k; }
    else             { W = Wv; bias = bv; out = g_v; }

    __shared__ float As[16][64];
    __shared__ float Bs[16][64];

    int tid = threadIdx.x;
    int tm = tid >> 4;
    int tn = tid & 15;
    int m0 = blockIdx.y * 64;
    int n0 = blockIdx.x * 64;
    int lr = tid >> 2;
    int lc = (tid & 3) << 2;

    const float* Aptr = X + (size_t)(m0 + lr) * DD + lc;
    const float* Wptr = W + (size_t)(n0 + lr) * DD + lc;

    float acc[4][4] = {};

    for (int k0 = 0; k0 < DD; k0 += 16) {
        float4 av = *(const float4*)(Aptr + k0);
        float4 wv = *(const float4*)(Wptr + k0);
        __syncthreads();
        As[lc + 0][lr] = av.x; As[lc + 1][lr] = av.y;
        As[lc + 2][lr] = av.z; As[lc + 3][lr] = av.w;
        Bs[lc + 0][lr] = wv.x; Bs[lc + 1][lr] = wv.y;
        Bs[lc + 2][lr] = wv.z; Bs[lc + 3][lr] = wv.w;
        __syncthreads();
        #pragma unroll
        for (int kk = 0; kk < 16; kk++) {
            float4 a4 = *(const float4*)&As[kk][tm * 4];
            float4 b4 = *(const float4*)&Bs[kk][tn * 4];
            float a[4] = {a4.x, a4.y, a4.z, a4.w};
            float b[4] = {b4.x, b4.y, b4.z, b4.w};
            #pragma unroll
            for (int i = 0; i < 4; i++)
                #pragma unroll
                for (int j = 0; j < 4; j++)
                    acc[i][j] = fmaf(a[i], b[j], acc[i][j]);
        }
    }

    int n = n0 + tn * 4;
    float4 bv4 = *(const float4*)&bias[n];
    int h = n >> 6;
    int hd = n & 63;
    #pragma unroll
    for (int i = 0; i < 4; i++) {
        int m = m0 + tm * 4 + i;
        int b = m >> 12;
        int s = m & (SS - 1);
        float4 r;
        r.x = acc[i][0] + bv4.x;
        r.y = acc[i][1] + bv4.y;
        r.z = acc[i][2] + bv4.z;
        r.w = acc[i][3] + bv4.w;
        *(float4*)&out[(((size_t)(b * HH + h) * SS + s) << 6) + hd] = r;
    }
}

__global__ __launch_bounds__(256) void out_gemm(
    const float* __restrict__ Wo, const float* __restrict__ bo,
    float* __restrict__ out)
{
    __shared__ float As[16][64];
    __shared__ float Bs[16][64];

    int tid = threadIdx.x;
    int tm = tid >> 4;
    int tn = tid & 15;
    int m0 = blockIdx.y * 64;
    int n0 = blockIdx.x * 64;
    int lr = tid >> 2;
    int lc = (tid & 3) << 2;

    const float* Aptr = g_attn + (size_t)(m0 + lr) * DD + lc;
    const float* Wptr = Wo     + (size_t)(n0 + lr) * DD + lc;

    float acc[4][4] = {};

    for (int k0 = 0; k0 < DD; k0 += 16) {
        float4 av = *(const float4*)(Aptr + k0);
        float4 wv = *(const float4*)(Wptr + k0);
        __syncthreads();
        As[lc + 0][lr] = av.x; As[lc + 1][lr] = av.y;
        As[lc + 2][lr] = av.z; As[lc + 3][lr] = av.w;
        Bs[lc + 0][lr] = wv.x; Bs[lc + 1][lr] = wv.y;
        Bs[lc + 2][lr] = wv.z; Bs[lc + 3][lr] = wv.w;
        __syncthreads();
        #pragma unroll
        for (int kk = 0; kk < 16; kk++) {
            float4 a4 = *(const float4*)&As[kk][tm * 4];
            float4 b4 = *(const float4*)&Bs[kk][tn * 4];
            float a[4] = {a4.x, a4.y, a4.z, a4.w};
            float b[4] = {b4.x, b4.y, b4.z, b4.w};
            #pragma unroll
            for (int i = 0; i < 4; i++)
                #pragma unroll
                for (int j = 0; j < 4; j++)
                    acc[i][j] = fmaf(a[i], b[j], acc[i][j]);
        }
    }

    int n = n0 + tn * 4;
    float4 bv4 = *(const float4*)&bo[n];
    #pragma unroll
    for (int i = 0; i < 4; i++) {
        int m = m0 + tm * 4 + i;
        float4 r;
        r.x = acc[i][0] + bv4.x;
        r.y = acc[i][1] + bv4.y;
        r.z = acc[i][2] + bv4.z;
        r.w = acc[i][3] + bv4.w;
        *(float4*)&out[(size_t)m * DD + n] = r;
    }
}

// ---------------------------------------------------------------------------
// Flash attention on tf32 mma.sync (m16n8k8).
// Block = 128 threads = 4 warps. Block covers 128 q-rows of one (b,h).
// Warp w owns rows [w*32, w*32+32). Streams 64-key tiles with online softmax.
//
// All smem operands are stored fragment-permuted: X[row][(col&7)*8 + col>>3],
// row stride 68 floats, so every mma fragment load is one LDS.128 pair.
// ---------------------------------------------------------------------------
#define QP_ROWS 128
#define STRD 68
// smem floats: Qp 128*68 | Kp 64*68 | Vp 64*68 | Pp 4*32*68
#define SM_QP 0
#define SM_KP (128*STRD)
#define SM_VP (SM_KP + 64*STRD)
#define SM_PP (SM_VP + 64*STRD)
#define SM_TOTAL_F (SM_PP + 4*32*STRD)

__global__ __launch_bounds__(128) void flash_attn()
{
    extern __shared__ float smf[];
    float* Qp = smf + SM_QP;
    float* Kp = smf + SM_KP;
    float* Vp = smf + SM_VP;
    float* Pp = smf + SM_PP;

    const int tid  = threadIdx.x;
    const int wid  = tid >> 5;
    const int lane = tid & 31;
    const int g    = lane >> 2;   // group id (row within m16 / col within n8)
    const int c    = lane & 3;    // thread-in-group (col within k8)
    const int bh   = blockIdx.y;
    const int q0   = blockIdx.x << 7;

    const float* Qg = g_q + (size_t)bh * SS * HDIM;
    const float* Kg = g_k + (size_t)bh * SS * HDIM;
    const float* Vg = g_v + (size_t)bh * SS * HDIM;

    // ---- stage Q (once), scaled by 1/8, tf32-rounded, permuted ----
    {
        const float4* src = (const float4*)(Qg + (size_t)(q0 + tid) * HDIM);
        float* dst = Qp + tid * STRD;
        #pragma unroll
        for (int v = 0; v < 16; v++) {
            float4 x = src[v];
            float vals[4] = {x.x, x.y, x.z, x.w};
            #pragma unroll
            for (int j = 0; j < 4; j++) {
                int col = 4*v + j;
                dst[(col & 7) * 8 + (col >> 3)] =
                    __uint_as_float(f2tf(vals[j] * 0.125f));
            }
        }
    }

    float O[2][8][4];
    #pragma unroll
    for (int t = 0; t < 2; t++)
        #pragma unroll
        for (int n = 0; n < 8; n++)
            #pragma unroll
            for (int i = 0; i < 4; i++) O[t][n][i] = 0.f;

    float mrow[2][2] = {{-1e30f, -1e30f}, {-1e30f, -1e30f}};
    float lrow[2][2] = {{0.f, 0.f}, {0.f, 0.f}};

    float* Ppw = Pp + wid * 32 * STRD;
    const int rowb = wid * 32;

    const int sr = tid & 63;          // staging row (key index)
    const int sh = (tid >> 6) * 32;   // staging col base (hd)

    for (int kt = 0; kt < SS / 64; kt++) {
        const int kb = kt << 6;
        __syncthreads();   // all warps done reading Kp/Vp from prev tile

        // ---- stage K, V (tf32, permuted) ----
        {
            const float4* ksrc = (const float4*)(Kg + (size_t)(kb + sr) * HDIM + sh);
            const float4* vsrc = (const float4*)(Vg + (size_t)(kb + sr) * HDIM + sh);
            float* krow = Kp + sr * STRD;
            const int vperm = (sr & 7) * 8 + (sr >> 3);
            #pragma unroll
            for (int v = 0; v < 8; v++) {
                float4 kx = ksrc[v];
                float4 vx = vsrc[v];
                float kvals[4] = {kx.x, kx.y, kx.z, kx.w};
                float vvals[4] = {vx.x, vx.y, vx.z, vx.w};
                #pragma unroll
                for (int j = 0; j < 4; j++) {
                    int col = sh + 4*v + j;
                    krow[(col & 7) * 8 + (col >> 3)] = __uint_as_float(f2tf(kvals[j]));
                    Vp[col * STRD + vperm]           = __uint_as_float(f2tf(vvals[j]));
                }
            }
        }
        __syncthreads();

        // ---- QK^T + online softmax, per m16 half ----
        #pragma unroll
        for (int t = 0; t < 2; t++) {
            const int rb = rowb + t * 16;
            unsigned qa0[8], qa1[8], qa2[8], qa3[8];
            ld8(qa0, Qp + (rb + g    ) * STRD +  c      * 8);
            ld8(qa1, Qp + (rb + g + 8) * STRD +  c      * 8);
            ld8(qa2, Qp + (rb + g    ) * STRD + (c + 4) * 8);
            ld8(qa3, Qp + (rb + g + 8) * STRD + (c + 4) * 8);

            float S[8][4];
            #pragma unroll
            for (int n = 0; n < 8; n++)
                #pragma unroll
                for (int i = 0; i < 4; i++) S[n][i] = 0.f;

            #pragma unroll
            for (int n = 0; n < 8; n++) {
                unsigned b0[8], b1[8];
                ld8(b0, Kp + (n*8 + g) * STRD +  c      * 8);
                ld8(b1, Kp + (n*8 + g) * STRD + (c + 4) * 8);
                #pragma unroll
                for (int s = 0; s < 8; s++)
                    mma_tf32(S[n], qa0[s], qa1[s], qa2[s], qa3[s], b0[s], b1[s]);
            }

            // online softmax (rows g and g+8 of this m16 tile)
            #pragma unroll
            for (int e = 0; e < 2; e++) {
                float mx = -1e30f;
                #pragma unroll
                for (int n = 0; n < 8; n++)
                    mx = fmaxf(mx, fmaxf(S[n][2*e], S[n][2*e+1]));
                mx = fmaxf(mx, __shfl_xor_sync(0xffffffffu, mx, 1));
                mx = fmaxf(mx, __shfl_xor_sync(0xffffffffu, mx, 2));
                float mold = mrow[t][e];
                float mnew = fmaxf(mold, mx);
                float f = __expf(mold - mnew);
                float rs = 0.f;
                #pragma unroll
                for (int n = 0; n < 8; n++) {
                    float p0 = __expf(S[n][2*e]   - mnew);
                    float p1 = __expf(S[n][2*e+1] - mnew);
                    S[n][2*e] = p0; S[n][2*e+1] = p1;
                    rs += p0 + p1;
                }
                rs += __shfl_xor_sync(0xffffffffu, rs, 1);
                rs += __shfl_xor_sync(0xffffffffu, rs, 2);
                lrow[t][e] = lrow[t][e] * f + rs;
                mrow[t][e] = mnew;
                #pragma unroll
                for (int n = 0; n < 8; n++) {
                    O[t][n][2*e]   *= f;
                    O[t][n][2*e+1] *= f;
                }
            }

            // store P (tf32, permuted) to warp-private region
            float* pr0 = Ppw + (t*16 + g    ) * STRD;
            float* pr1 = Ppw + (t*16 + g + 8) * STRD;
            #pragma unroll
            for (int n = 0; n < 8; n++) {
                pr0[(2*c    ) * 8 + n] = __uint_as_float(f2tf(S[n][0]));
                pr0[(2*c + 1) * 8 + n] = __uint_as_float(f2tf(S[n][1]));
                pr1[(2*c    ) * 8 + n] = __uint_as_float(f2tf(S[n][2]));
                pr1[(2*c + 1) * 8 + n] = __uint_as_float(f2tf(S[n][3]));
            }
        }
        __syncwarp();

        // ---- P @ V ----
        unsigned pa[2][4][8];
        #pragma unroll
        for (int t = 0; t < 2; t++) {
            ld8(pa[t][0], Ppw + (t*16 + g    ) * STRD +  c      * 8);
            ld8(pa[t][1], Ppw + (t*16 + g + 8) * STRD +  c      * 8);
            ld8(pa[t][2], Ppw + (t*16 + g    ) * STRD + (c + 4) * 8);
            ld8(pa[t][3], Ppw + (t*16 + g + 8) * STRD + (c + 4) * 8);
        }
        #pragma unroll
        for (int n = 0; n < 8; n++) {
            unsigned vb0[8], vb1[8];
            ld8(vb0, Vp + (n*8 + g) * STRD +  c      * 8);
            ld8(vb1, Vp + (n*8 + g) * STRD + (c + 4) * 8);
            #pragma unroll
            for (int s = 0; s < 8; s++) {
                mma_tf32(O[0][n], pa[0][0][s], pa[0][1][s], pa[0][2][s], pa[0][3][s],
                         vb0[s], vb1[s]);
                mma_tf32(O[1][n], pa[1][0][s], pa[1][1][s], pa[1][2][s], pa[1][3][s],
                         vb0[s], vb1[s]);
            }
        }
    }

    // ---- epilogue: O / l -> g_attn [B,S,D] ----
    const int b = bh >> 3;
    const int h = bh & 7;
    #pragma unroll
    for (int t = 0; t < 2; t++)
        #pragma unroll
        for (int e = 0; e < 2; e++) {
            float inv = 1.f / lrow[t][e];
            int row = q0 + rowb + t*16 + g + 8*e;
            float* dst = g_attn + (size_t)(b * SS + row) * DD + h * HDIM;
            #pragma unroll
            for (int n = 0; n < 8; n++) {
                float2 val = make_float2(O[t][n][2*e] * inv, O[t][n][2*e+1] * inv);
                *(float2*)(dst + n*8 + 2*c) = val;
            }
        }
}

// ---------------------------------------------------------------------------
extern "C" void kernel_launch(void* const* d_in, const int* in_sizes, int n_in,
                              void* d_out, int out_size)
{
    (void)in_sizes; (void)n_in; (void)out_size;
    const float* x  = (const float*)d_in[0];
    const float* Wq = (const float*)d_in[1];
    const float* bq = (const float*)d_in[2];
    const float* Wk = (const float*)d_in[3];
    const float* bk = (const float*)d_in[4];
    const float* Wv = (const float*)d_in[5];
    const float* bv = (const float*)d_in[6];
    const float* Wo = (const float*)d_in[7];
    const float* bo = (const float*)d_in[8];
    float* out = (float*)d_out;

    dim3 gqkv(DD / 64, MTOT / 64, 3);
    qkv_gemm<<<gqkv, 256>>>(x, Wq, bq, Wk, bk, Wv, bv);

    static int smem_set = 0;
    const int smem_bytes = SM_TOTAL_F * (int)sizeof(float);
    if (!smem_set) {
        cudaFuncSetAttribute(flash_attn,
                             cudaFuncAttributeMaxDynamicSharedMemorySize,
                             smem_bytes);
        smem_set = 1;
    }
    dim3 gat(SS / 128, BB * HH);          // (32, 16)
    flash_attn<<<gat, 128, smem_bytes>>>();

    dim3 go(DD / 64, MTOT / 64);
    out_gemm<<<go, 256>>>(Wo, bo, out);
}

// round 3
// speedup vs baseline: 1.9576x; 1.2424x over previous
#include <cuda_runtime.h>

#define BB 2
#define SS 4096
#define DD 512
#define HH 8
#define HDIM 64
#define MTOT (BB*SS)
#define STRD 68

// Scratch (allocation-free rule: device globals)
// g_q: [bh][s][perm(hd)]   tf32, pre-scaled by 0.125
// g_k: [bh][s][perm(hd)]   tf32
// g_v: [bh][kt][hd][perm(key-in-tile)] tf32  (transposed per 64-key tile)
// g_attn: [B,S,D] fp32
__device__ float g_q[BB*HH*SS*HDIM];
__device__ float g_k[BB*HH*SS*HDIM];
__device__ float g_v[BB*HH*SS*HDIM];
__device__ float g_attn[BB*SS*DD];

// ---------------------------------------------------------------------------
// helpers
// ---------------------------------------------------------------------------
__device__ __forceinline__ unsigned f2tf(float f) {
    unsigned u;
    asm("cvt.rna.tf32.f32 %0, %1;" : "=r"(u) : "f"(f));
    return u;
}

__device__ __forceinline__ void mma_tf32(float c[4],
    unsigned a0, unsigned a1, unsigned a2, unsigned a3,
    unsigned b0, unsigned b1)
{
    asm volatile(
        "mma.sync.aligned.m16n8k8.row.col.f32.tf32.tf32.f32 "
        "{%0,%1,%2,%3}, {%4,%5,%6,%7}, {%8,%9}, {%0,%1,%2,%3};"
        : "+f"(c[0]), "+f"(c[1]), "+f"(c[2]), "+f"(c[3])
        : "r"(a0), "r"(a1), "r"(a2), "r"(a3), "r"(b0), "r"(b1));
}

__device__ __forceinline__ void ld8(unsigned* dst, const float* base) {
    uint4 a = *(const uint4*)base;
    uint4 b = *(const uint4*)(base + 4);
    dst[0]=a.x; dst[1]=a.y; dst[2]=a.z; dst[3]=a.w;
    dst[4]=b.x; dst[5]=b.y; dst[6]=b.z; dst[7]=b.w;
}

// ---------------------------------------------------------------------------
// tf32 MMA NT-GEMM: C[m,n] = sum_k A[m,k]*W[n,k] + bias[n]
// 128x128 block tile, 256 threads (8 warps: 4 m-groups x 2 n-groups),
// warp tile 32x64 (2 m16 x 8 n8), K-tile 64, fragment-permuted smem.
// mode: 0=Q epilogue (scaled, permuted), 1=K (permuted), 2=V (transposed),
//       3=plain fp32 out (A taken from g_attn).
// ---------------------------------------------------------------------------
__global__ __launch_bounds__(256) void proj_gemm(
    const float* __restrict__ A_in, const float* __restrict__ W,
    const float* __restrict__ bias, float* __restrict__ outp, int mode)
{
    extern __shared__ float sm[];
    float* As = sm;
    float* Ws = sm + 128 * STRD;

    const float* A = (mode == 3) ? (const float*)g_attn : A_in;

    const int tid  = threadIdx.x;
    const int wid  = tid >> 5;
    const int lane = tid & 31;
    const int g    = lane >> 2;
    const int c    = lane & 3;
    const int warp_m = wid & 3;
    const int warp_n = wid >> 2;
    const int m_base = blockIdx.y * 128;
    const int n_base = blockIdx.x * 128;

    const int lr = tid >> 1;            // 0..127
    const int lc = (tid & 1) * 32;      // 0 or 32

    const float* Arow = A + (size_t)(m_base + lr) * DD + lc;
    const float* Wrow = W + (size_t)(n_base + lr) * DD + lc;

    float S[2][8][4];
    #pragma unroll
    for (int t = 0; t < 2; t++)
        #pragma unroll
        for (int n = 0; n < 8; n++)
            #pragma unroll
            for (int i = 0; i < 4; i++) S[t][n][i] = 0.f;

    for (int k0 = 0; k0 < DD; k0 += 64) {
        __syncthreads();
        // stage A and W tiles: tf32 convert + fragment-permute
        #pragma unroll
        for (int v = 0; v < 8; v++) {
            float4 a = *(const float4*)(Arow + k0 + 4*v);
            float4 w = *(const float4*)(Wrow + k0 + 4*v);
            float av[4] = {a.x, a.y, a.z, a.w};
            float wv[4] = {w.x, w.y, w.z, w.w};
            #pragma unroll
            for (int j = 0; j < 4; j++) {
                int col = lc + 4*v + j;
                int p = ((col & 7) << 3) + (col >> 3);
                As[lr * STRD + p] = __uint_as_float(f2tf(av[j]));
                Ws[lr * STRD + p] = __uint_as_float(f2tf(wv[j]));
            }
        }
        __syncthreads();

        unsigned qa[2][4][8];
        #pragma unroll
        for (int t = 0; t < 2; t++) {
            int rb = warp_m * 32 + t * 16;
            ld8(qa[t][0], As + (rb + g    ) * STRD +  c      * 8);
            ld8(qa[t][1], As + (rb + g + 8) * STRD +  c      * 8);
            ld8(qa[t][2], As + (rb + g    ) * STRD + (c + 4) * 8);
            ld8(qa[t][3], As + (rb + g + 8) * STRD + (c + 4) * 8);
        }
        #pragma unroll
        for (int n = 0; n < 8; n++) {
            unsigned b0[8], b1[8];
            int bn = warp_n * 64 + n * 8 + g;
            ld8(b0, Ws + bn * STRD +  c      * 8);
            ld8(b1, Ws + bn * STRD + (c + 4) * 8);
            #pragma unroll
            for (int s = 0; s < 8; s++) {
                mma_tf32(S[0][n], qa[0][0][s], qa[0][1][s], qa[0][2][s], qa[0][3][s], b0[s], b1[s]);
                mma_tf32(S[1][n], qa[1][0][s], qa[1][1][s], qa[1][2][s], qa[1][3][s], b0[s], b1[s]);
            }
        }
    }

    // epilogue
    if (mode == 3) {
        #pragma unroll
        for (int t = 0; t < 2; t++) {
            int row0 = m_base + warp_m * 32 + t * 16 + g;
            #pragma unroll
            for (int n = 0; n < 8; n++) {
                int col = n_base + warp_n * 64 + n * 8 + 2 * c;
                float2 b2 = *(const float2*)&bias[col];
                float2 r0 = make_float2(S[t][n][0] + b2.x, S[t][n][1] + b2.y);
                float2 r1 = make_float2(S[t][n][2] + b2.x, S[t][n][3] + b2.y);
                *(float2*)&outp[(size_t)row0 * DD + col]       = r0;
                *(float2*)&outp[(size_t)(row0 + 8) * DD + col] = r1;
            }
        }
        return;
    }

    const float sc = (mode == 0) ? 0.125f : 1.0f;
    float* gout = (mode == 0) ? g_q : (mode == 1) ? g_k : g_v;

    #pragma unroll
    for (int t = 0; t < 2; t++) {
        #pragma unroll
        for (int n = 0; n < 8; n++) {
            int col = n_base + warp_n * 64 + n * 8 + 2 * c;
            float2 b2 = *(const float2*)&bias[col];
            int h   = col >> 6;
            int hd0 = col & 63;
            int hd1 = hd0 + 1;
            int p0 = ((hd0 & 7) << 3) + (hd0 >> 3);
            int p1 = ((hd1 & 7) << 3) + (hd1 >> 3);
            #pragma unroll
            for (int e = 0; e < 2; e++) {
                int r  = m_base + warp_m * 32 + t * 16 + g + 8 * e;
                float v0 = (S[t][n][2*e]   + b2.x) * sc;
                float v1 = (S[t][n][2*e+1] + b2.y) * sc;
                int b  = r >> 12;
                int s2 = r & (SS - 1);
                int bh = b * HH + h;
                if (mode <= 1) {
                    float* dst = gout + ((size_t)bh * SS + s2) * 64;
                    dst[p0] = __uint_as_float(f2tf(v0));
                    dst[p1] = __uint_as_float(f2tf(v1));
                } else {
                    int kt = s2 >> 6;
                    int kk = s2 & 63;
                    int pk = ((kk & 7) << 3) + (kk >> 3);
                    float* dst = gout + ((size_t)(bh * 64 + kt) << 12) + pk;
                    dst[hd0 * 64] = __uint_as_float(f2tf(v0));
                    dst[hd1 * 64] = __uint_as_float(f2tf(v1));
                }
            }
        }
    }
}

// ---------------------------------------------------------------------------
// Flash attention on tf32 mma.sync. Block = 128 threads = 4 warps, 128 q-rows.
// Inputs pre-converted/permuted by proj_gemm; staging is pure float4 copies.
// Q fragments hoisted into registers for the whole kernel; K fragments loaded
// once per tile and shared across both m16 halves.
// ---------------------------------------------------------------------------
#define SM_QP 0
#define SM_KP (128*STRD)
#define SM_VP (SM_KP + 64*STRD)
#define SM_PP (SM_VP + 64*STRD)
#define SM_TOTAL_F (SM_PP + 4*32*STRD)

__global__ __launch_bounds__(128) void flash_attn()
{
    extern __shared__ float smf[];
    float* Qp = smf + SM_QP;
    float* Kp = smf + SM_KP;
    float* Vp = smf + SM_VP;
    float* Pp = smf + SM_PP;

    const int tid  = threadIdx.x;
    const int wid  = tid >> 5;
    const int lane = tid & 31;
    const int g    = lane >> 2;
    const int c    = lane & 3;
    const int bh   = blockIdx.y;
    const int q0   = blockIdx.x << 7;

    const float* Qg = g_q + (size_t)bh * SS * HDIM;
    const float* Kg = g_k + (size_t)bh * SS * HDIM;
    const float* Vg = g_v + ((size_t)bh << 18);   // bh * 64 tiles * 4096

    // stage Q (already tf32+scaled+permuted): plain copy
    {
        const float4* src = (const float4*)(Qg + (size_t)(q0 + tid) * HDIM);
        float4* dst = (float4*)(Qp + tid * STRD);
        #pragma unroll
        for (int v = 0; v < 16; v++) dst[v] = src[v];
    }
    __syncthreads();

    // hoist Q fragments for the whole kernel
    const int rowb = wid * 32;
    unsigned qa[2][4][8];
    #pragma unroll
    for (int t = 0; t < 2; t++) {
        int rb = rowb + t * 16;
        ld8(qa[t][0], Qp + (rb + g    ) * STRD +  c      * 8);
        ld8(qa[t][1], Qp + (rb + g + 8) * STRD +  c      * 8);
        ld8(qa[t][2], Qp + (rb + g    ) * STRD + (c + 4) * 8);
        ld8(qa[t][3], Qp + (rb + g + 8) * STRD + (c + 4) * 8);
    }

    float O[2][8][4];
    #pragma unroll
    for (int t = 0; t < 2; t++)
        #pragma unroll
        for (int n = 0; n < 8; n++)
            #pragma unroll
            for (int i = 0; i < 4; i++) O[t][n][i] = 0.f;

    float mrow[2][2] = {{-1e30f, -1e30f}, {-1e30f, -1e30f}};
    float lrow[2][2] = {{0.f, 0.f}, {0.f, 0.f}};

    float* Ppw = Pp + wid * 32 * STRD;
    const int sr = tid & 63;
    const int sh = (tid >> 6) * 32;

    for (int kt = 0; kt < SS / 64; kt++) {
        const int kb = kt << 6;
        __syncthreads();   // prior tile fully consumed

        // stage K, V: plain float4 copies (pre-permuted in gmem)
        {
            const float4* ks = (const float4*)(Kg + (size_t)(kb + sr) * HDIM + sh);
            const float4* vs = (const float4*)(Vg + ((size_t)kt << 12) + sr * 64 + sh);
            float4* kd = (float4*)(Kp + sr * STRD + sh);
            float4* vd = (float4*)(Vp + sr * STRD + sh);
            #pragma unroll
            for (int v = 0; v < 8; v++) { kd[v] = ks[v]; vd[v] = vs[v]; }
        }
        __syncthreads();

        // QK^T: both m16 halves share each K fragment
        float S[2][8][4];
        #pragma unroll
        for (int t = 0; t < 2; t++)
            #pragma unroll
            for (int n = 0; n < 8; n++)
                #pragma unroll
                for (int i = 0; i < 4; i++) S[t][n][i] = 0.f;

        #pragma unroll
        for (int n = 0; n < 8; n++) {
            unsigned b0[8], b1[8];
            ld8(b0, Kp + (n*8 + g) * STRD +  c      * 8);
            ld8(b1, Kp + (n*8 + g) * STRD + (c + 4) * 8);
            #pragma unroll
            for (int s = 0; s < 8; s++) {
                mma_tf32(S[0][n], qa[0][0][s], qa[0][1][s], qa[0][2][s], qa[0][3][s], b0[s], b1[s]);
                mma_tf32(S[1][n], qa[1][0][s], qa[1][1][s], qa[1][2][s], qa[1][3][s], b0[s], b1[s]);
            }
        }

        // online softmax + vectorized P store
        #pragma unroll
        for (int t = 0; t < 2; t++) {
            #pragma unroll
            for (int e = 0; e < 2; e++) {
                float mx = -1e30f;
                #pragma unroll
                for (int n = 0; n < 8; n++)
                    mx = fmaxf(mx, fmaxf(S[t][n][2*e], S[t][n][2*e+1]));
                mx = fmaxf(mx, __shfl_xor_sync(0xffffffffu, mx, 1));
                mx = fmaxf(mx, __shfl_xor_sync(0xffffffffu, mx, 2));
                float mold = mrow[t][e];
                float mnew = fmaxf(mold, mx);
                float f = __expf(mold - mnew);
                float rs = 0.f;
                #pragma unroll
                for (int n = 0; n < 8; n++) {
                    float p0 = __expf(S[t][n][2*e]   - mnew);
                    float p1 = __expf(S[t][n][2*e+1] - mnew);
                    S[t][n][2*e] = p0; S[t][n][2*e+1] = p1;
                    rs += p0 + p1;
                }
                rs += __shfl_xor_sync(0xffffffffu, rs, 1);
                rs += __shfl_xor_sync(0xffffffffu, rs, 2);
                lrow[t][e] = lrow[t][e] * f + rs;
                mrow[t][e] = mnew;
                #pragma unroll
                for (int n = 0; n < 8; n++) {
                    O[t][n][2*e]   *= f;
                    O[t][n][2*e+1] *= f;
                }
            }
            // P[row][j=n*8+2c+i] -> physical (2c+i)*8+n : 16 consecutive floats/row
            float* pr0 = Ppw + (t*16 + g    ) * STRD + 16*c;
            float* pr1 = Ppw + (t*16 + g + 8) * STRD + 16*c;
            float4 x;
            x = make_float4(__uint_as_float(f2tf(S[t][0][0])), __uint_as_float(f2tf(S[t][1][0])),
                            __uint_as_float(f2tf(S[t][2][0])), __uint_as_float(f2tf(S[t][3][0])));
            *(float4*)(pr0 + 0) = x;
            x = make_float4(__uint_as_float(f2tf(S[t][4][0])), __uint_as_float(f2tf(S[t][5][0])),
                            __uint_as_float(f2tf(S[t][6][0])), __uint_as_float(f2tf(S[t][7][0])));
            *(float4*)(pr0 + 4) = x;
            x = make_float4(__uint_as_float(f2tf(S[t][0][1])), __uint_as_float(f2tf(S[t][1][1])),
                            __uint_as_float(f2tf(S[t][2][1])), __uint_as_float(f2tf(S[t][3][1])));
            *(float4*)(pr0 + 8) = x;
            x = make_float4(__uint_as_float(f2tf(S[t][4][1])), __uint_as_float(f2tf(S[t][5][1])),
                            __uint_as_float(f2tf(S[t][6][1])), __uint_as_float(f2tf(S[t][7][1])));
            *(float4*)(pr0 + 12) = x;
            x = make_float4(__uint_as_float(f2tf(S[t][0][2])), __uint_as_float(f2tf(S[t][1][2])),
                            __uint_as_float(f2tf(S[t][2][2])), __uint_as_float(f2tf(S[t][3][2])));
            *(float4*)(pr1 + 0) = x;
            x = make_float4(__uint_as_float(f2tf(S[t][4][2])), __uint_as_float(f2tf(S[t][5][2])),
                            __uint_as_float(f2tf(S[t][6][2])), __uint_as_float(f2tf(S[t][7][2])));
            *(float4*)(pr1 + 4) = x;
            x = make_float4(__uint_as_float(f2tf(S[t][0][3])), __uint_as_float(f2tf(S[t][1][3])),
                            __uint_as_float(f2tf(S[t][2][3])), __uint_as_float(f2tf(S[t][3][3])));
            *(float4*)(pr1 + 8) = x;
            x = make_float4(__uint_as_float(f2tf(S[t][4][3])), __uint_as_float(f2tf(S[t][5][3])),
                            __uint_as_float(f2tf(S[t][6][3])), __uint_as_float(f2tf(S[t][7][3])));
            *(float4*)(pr1 + 12) = x;
        }
        __syncwarp();

        // P @ V (V fragments shared across both m16 halves)
        unsigned pa[2][4][8];
        #pragma unroll
        for (int t = 0; t < 2; t++) {
            ld8(pa[t][0], Ppw + (t*16 + g    ) * STRD +  c      * 8);
            ld8(pa[t][1], Ppw + (t*16 + g + 8) * STRD +  c      * 8);
            ld8(pa[t][2], Ppw + (t*16 + g    ) * STRD + (c + 4) * 8);
            ld8(pa[t][3], Ppw + (t*16 + g + 8) * STRD + (c + 4) * 8);
        }
        #pragma unroll
        for (int n = 0; n < 8; n++) {
            unsigned vb0[8], vb1[8];
            ld8(vb0, Vp + (n*8 + g) * STRD +  c      * 8);
            ld8(vb1, Vp + (n*8 + g) * STRD + (c + 4) * 8);
            #pragma unroll
            for (int s = 0; s < 8; s++) {
                mma_tf32(O[0][n], pa[0][0][s], pa[0][1][s], pa[0][2][s], pa[0][3][s], vb0[s], vb1[s]);
                mma_tf32(O[1][n], pa[1][0][s], pa[1][1][s], pa[1][2][s], pa[1][3][s], vb0[s], vb1[s]);
            }
        }
    }

    // epilogue: O / l -> g_attn [B,S,D]
    const int b = bh >> 3;
    const int h = bh & 7;
    #pragma unroll
    for (int t = 0; t < 2; t++)
        #pragma unroll
        for (int e = 0; e < 2; e++) {
            float inv = 1.f / lrow[t][e];
            int row = q0 + rowb + t*16 + g + 8*e;
            float* dst = g_attn + (size_t)(b * SS + row) * DD + h * HDIM;
            #pragma unroll
            for (int n = 0; n < 8; n++) {
                float2 val = make_float2(O[t][n][2*e] * inv, O[t][n][2*e+1] * inv);
                *(float2*)(dst + n*8 + 2*c) = val;
            }
        }
}

// ---------------------------------------------------------------------------
extern "C" void kernel_launch(void* const* d_in, const int* in_sizes, int n_in,
                              void* d_out, int out_size)
{
    (void)in_sizes; (void)n_in; (void)out_size;
    const float* x  = (const float*)d_in[0];
    const float* Wq = (const float*)d_in[1];
    const float* bq = (const float*)d_in[2];
    const float* Wk = (const float*)d_in[3];
    const float* bk = (const float*)d_in[4];
    const float* Wv = (const float*)d_in[5];
    const float* bv = (const float*)d_in[6];
    const float* Wo = (const float*)d_in[7];
    const float* bo = (const float*)d_in[8];
    float* out = (float*)d_out;

    const int gemm_smem  = 2 * 128 * STRD * (int)sizeof(float);   // 69632
    const int flash_smem = SM_TOTAL_F * (int)sizeof(float);       // 104448

    static int attr_set = 0;
    if (!attr_set) {
        cudaFuncSetAttribute(proj_gemm,
            cudaFuncAttributeMaxDynamicSharedMemorySize, gemm_smem);
        cudaFuncSetAttribute(flash_attn,
            cudaFuncAttributeMaxDynamicSharedMemorySize, flash_smem);
        attr_set = 1;
    }

    dim3 gp(DD / 128, MTOT / 128);        // (4, 64)
    proj_gemm<<<gp, 256, gemm_smem>>>(x, Wq, bq, nullptr, 0);
    proj_gemm<<<gp, 256, gemm_smem>>>(x, Wk, bk, nullptr, 1);
    proj_gemm<<<gp, 256, gemm_smem>>>(x, Wv, bv, nullptr, 2);

    dim3 gat(SS / 128, BB * HH);          // (32, 16)
    flash_attn<<<gat, 128, flash_smem>>>();

    proj_gemm<<<gp, 256, gemm_smem>>>(nullptr, Wo, bo, out, 3);
}